// round 14
// baseline (speedup 1.0000x reference)
#include <cuda_runtime.h>
#include <cuda_fp16.h>

#define IMG_H 1024
#define IMG_W 1024
#define IMG_HW (IMG_H * IMG_W)
#define WS 128
#define HALF 64
#define NE 6
#define NF 7
#define DH 16
#define NC 512
#define PX_PER_C (WS * WS)
#define PROB_ELEMS (NC * PX_PER_C)

#define THREADS 256          // 8 warps
#define BLOCKS_X 2           // 2 x 64 rows; each warp loops over 8 rows
#define ROWS_PER_WARP 8
#define PADW 136             // half2 words per pair-plane; conflict-free LDS.128

// pack two f32 -> f16x2 (rn); first arg lands in the LOW half
__device__ __forceinline__ unsigned cvt2h(float lo, float hi) {
    unsigned r; asm("cvt.rn.f16x2.f32 %0, %1, %2;" : "=r"(r) : "f"(hi), "f"(lo)); return r;
}
__device__ __forceinline__ unsigned max2z(unsigned v) {
    unsigned r; asm("max.f16x2 %0, %1, %2;" : "=r"(r) : "r"(v), "r"(0u)); return r;
}
// m16n8k8, all-f16
__device__ __forceinline__ void mma8h(unsigned& d0, unsigned& d1,
                                      unsigned a0, unsigned a1,
                                      unsigned b0,
                                      unsigned c0, unsigned c1) {
    asm volatile(
        "mma.sync.aligned.m16n8k8.row.col.f16.f16.f16.f16 "
        "{%0,%1}, {%2,%3}, {%4}, {%5,%6};"
        : "=r"(d0), "=r"(d1)
        : "r"(a0), "r"(a1), "r"(b0), "r"(c0), "r"(c1));
}
// m16n8k16, all-f16
__device__ __forceinline__ void mma16h(unsigned& d0, unsigned& d1,
                                       unsigned a0, unsigned a1, unsigned a2, unsigned a3,
                                       unsigned b0, unsigned b1,
                                       unsigned c0, unsigned c1) {
    asm volatile(
        "mma.sync.aligned.m16n8k16.row.col.f16.f16.f16.f16 "
        "{%0,%1}, {%2,%3,%4,%5}, {%6,%7}, {%8,%9};"
        : "=r"(d0), "=r"(d1)
        : "r"(a0), "r"(a1), "r"(a2), "r"(a3), "r"(b0), "r"(b1), "r"(c0), "r"(c1));
}
// m16n8k16, f16 in, f32 accumulate (final layer)
__device__ __forceinline__ void mma16f(float& d0, float& d1, float& d2, float& d3,
                                       unsigned a0, unsigned a1, unsigned a2, unsigned a3,
                                       unsigned b0, unsigned b1,
                                       float c0, float c1, float c2, float c3) {
    asm volatile(
        "mma.sync.aligned.m16n8k16.row.col.f32.f16.f16.f32 "
        "{%0,%1,%2,%3}, {%4,%5,%6,%7}, {%8,%9}, {%10,%11,%12,%13};"
        : "=f"(d0), "=f"(d1), "=f"(d2), "=f"(d3)
        : "r"(a0), "r"(a1), "r"(a2), "r"(a3), "r"(b0), "r"(b1),
          "f"(c0), "f"(c1), "f"(c2), "f"(c3));
}

__global__ __launch_bounds__(THREADS, 4)
void instanseg_kernel(const float* __restrict__ x,
                      const float* __restrict__ sigma,
                      const float* __restrict__ cvec,
                      const float* __restrict__ W1,
                      const float* __restrict__ b1,
                      const float* __restrict__ W2,
                      const float* __restrict__ b2,
                      const float* __restrict__ W3,
                      const float* __restrict__ b3,
                      const int*   __restrict__ cent,
                      float* __restrict__ out,
                      int write_iidd)
{
    __shared__ float b1cs[DH];                             // b1 - c[cid] @ W1[0:6]
    __shared__ __align__(16) unsigned h2buf[8][4 * PADW];  // [warp][pair][px] half2
    __shared__ int cy0s, cx0s;

    const int tid  = threadIdx.x;
    const int wid  = tid >> 5;
    const int lane = tid & 31;
    const int g_   = lane >> 2;
    const int c_   = lane & 3;
    const int cid  = blockIdx.y;

    if (tid < DH) {
        float acc = b1[tid];
        #pragma unroll
        for (int e = 0; e < NE; e++)
            acc -= cvec[cid * NE + e] * W1[e * DH + tid];
        b1cs[tid] = acc;
    }
    if (tid == 0) {
        int cy = cent[cid * 2 + 0];
        int cx = cent[cid * 2 + 1];
        cy = min(max(cy, HALF), IMG_H - HALF);
        cx = min(max(cx, HALF), IMG_W - HALF);
        cy0s = cy - HALF;
        cx0s = cx - HALF;
    }
    __syncthreads();

    const int cy0 = cy0s, cx0 = cx0s;

    // ---- weight fragments (packed f16x2), loaded ONCE for 8 rows ----
    unsigned w1f[2], bias1h[2];
    #pragma unroll
    for (int t = 0; t < 2; t++) {
        int n = 8 * t + g_;
        float w0  = W1[(2 * c_) * DH + n];
        float w1v = (2 * c_ + 1 < NF) ? W1[(2 * c_ + 1) * DH + n] : 0.0f;
        w1f[t] = cvt2h(w0, w1v);
        bias1h[t] = cvt2h(b1cs[8 * t + 2 * c_], b1cs[8 * t + 2 * c_ + 1]);
    }
    unsigned w2f[2][2], bias2h[2];
    #pragma unroll
    for (int t = 0; t < 2; t++) {
        int n = 8 * t + g_;
        w2f[t][0] = cvt2h(W2[(2 * c_)     * DH + n], W2[(2 * c_ + 1) * DH + n]);
        w2f[t][1] = cvt2h(W2[(2 * c_ + 8) * DH + n], W2[(2 * c_ + 9) * DH + n]);
        bias2h[t] = cvt2h(b2[8 * t + 2 * c_], b2[8 * t + 2 * c_ + 1]);
    }
    unsigned w3f[2];
    w3f[0] = cvt2h(W3[2 * c_],     W3[2 * c_ + 1]);
    w3f[1] = cvt2h(W3[2 * c_ + 8], W3[2 * c_ + 9]);
    const float b3v = b3[0];

    unsigned* fw = h2buf[wid];
    const unsigned* fp = fw + c_ * PADW + 4 * g_;

    // ---- row loop: stage row -> MMA loop -> next row ----
    for (int r = 0; r < ROWS_PER_WARP; r++) {
        const int gy  = blockIdx.x * 64 + r * 8 + wid;
        const int row = cy0 + gy;

        // stage this row as pre-packed half2 feature pairs
        {
            const long roff = (long)row * IMG_W + cx0;
            #pragma unroll
            for (int p = 0; p < 3; p++) {
                const float* f0 = x + (2 * p)     * IMG_HW + roff;
                const float* f1 = x + (2 * p + 1) * IMG_HW + roff;
                #pragma unroll
                for (int q = 0; q < 4; q++) {
                    int col = q * 32 + lane;
                    fw[p * PADW + col] = cvt2h(f0[col], f1[col]);
                }
            }
            const float* fs = sigma + roff;
            #pragma unroll
            for (int q = 0; q < 4; q++) {
                int col = q * 32 + lane;
                fw[3 * PADW + col] = cvt2h(fs[col], 0.0f);
            }
        }
        __syncwarp();

        const long rowstart = (long)cid * PX_PER_C + (long)gy * WS;
        float* oplane = out + rowstart + 4 * g_ + c_;

        // software pipeline: prefetch iter-0 operands
        uint4 av = *(const uint4*)(fp);

        #pragma unroll
        for (int it = 0; it < 4; it++) {
            const int o = it * 32;
            uint4 cur = av;
            if (it < 3) av = *(const uint4*)(fp + o + 32);

            // ===== tile A =====
            unsigned d1a[2][2];
            #pragma unroll
            for (int t = 0; t < 2; t++)
                mma8h(d1a[t][0], d1a[t][1], cur.x, cur.y, w1f[t], bias1h[t], bias1h[t]);
            unsigned A0 = max2z(d1a[0][0]), A1 = max2z(d1a[0][1]);
            unsigned A2 = max2z(d1a[1][0]), A3 = max2z(d1a[1][1]);

            unsigned d2a[2][2];
            #pragma unroll
            for (int t = 0; t < 2; t++)
                mma16h(d2a[t][0], d2a[t][1], A0, A1, A2, A3,
                       w2f[t][0], w2f[t][1], bias2h[t], bias2h[t]);
            unsigned Ba0 = max2z(d2a[0][0]), Ba1 = max2z(d2a[0][1]);
            unsigned Ba2 = max2z(d2a[1][0]), Ba3 = max2z(d2a[1][1]);

            float d3a[4];
            mma16f(d3a[0], d3a[1], d3a[2], d3a[3],
                   Ba0, Ba1, Ba2, Ba3, w3f[0], w3f[1],
                   b3v, b3v, b3v, b3v);

            // ===== tile B =====
            unsigned d1b[2][2];
            #pragma unroll
            for (int t = 0; t < 2; t++)
                mma8h(d1b[t][0], d1b[t][1], cur.z, cur.w, w1f[t], bias1h[t], bias1h[t]);
            unsigned C0 = max2z(d1b[0][0]), C1 = max2z(d1b[0][1]);
            unsigned C2 = max2z(d1b[1][0]), C3 = max2z(d1b[1][1]);

            unsigned d2b[2][2];
            #pragma unroll
            for (int t = 0; t < 2; t++)
                mma16h(d2b[t][0], d2b[t][1], C0, C1, C2, C3,
                       w2f[t][0], w2f[t][1], bias2h[t], bias2h[t]);
            unsigned Bb0 = max2z(d2b[0][0]), Bb1 = max2z(d2b[0][1]);
            unsigned Bb2 = max2z(d2b[1][0]), Bb3 = max2z(d2b[1][1]);

            float d3b[4];
            mma16f(d3b[0], d3b[1], d3b[2], d3b[3],
                   Bb0, Bb1, Bb2, Bb3, w3f[0], w3f[1],
                   b3v, b3v, b3v, b3v);

            // all-lane sigmoid + coalesced STG.32
            float z0 = (c_ & 2) ? d3b[0] : d3a[0];
            float z1 = (c_ & 2) ? d3b[2] : d3a[2];
            float z  = (c_ & 1) ? z1 : z0;
            oplane[o] = __fdividef(1.0f, 1.0f + __expf(-z));
        }

        // iidd: pure index math, three coalesced STG.128 per row
        if (write_iidd) {
            const float fcid = (float)cid;
            const float frow = (float)row;
            const float fc0  = (float)(cx0 + 4 * lane);
            float4 vc = make_float4(fcid, fcid, fcid, fcid);
            float4 vr = make_float4(frow, frow, frow, frow);
            float4 vx = make_float4(fc0, fc0 + 1.0f, fc0 + 2.0f, fc0 + 3.0f);
            *(float4*)(out + PROB_ELEMS      + rowstart + 4 * lane) = vc;
            *(float4*)(out + 2L * PROB_ELEMS + rowstart + 4 * lane) = vr;
            *(float4*)(out + 3L * PROB_ELEMS + rowstart + 4 * lane) = vx;
        }
        __syncwarp();   // all lanes done reading fw before next row's staging
    }
}

extern "C" void kernel_launch(void* const* d_in, const int* in_sizes, int n_in,
                              void* d_out, int out_size)
{
    const float* x     = (const float*)d_in[0];
    const float* sigma = (const float*)d_in[1];
    const float* cvec  = (const float*)d_in[2];
    const float* W1    = (const float*)d_in[3];
    const float* b1    = (const float*)d_in[4];
    const float* W2    = (const float*)d_in[5];
    const float* b2    = (const float*)d_in[6];
    const float* W3    = (const float*)d_in[7];
    const float* b3    = (const float*)d_in[8];
    const int*   cent  = (const int*)d_in[9];
    float* out = (float*)d_out;

    int write_iidd = (out_size >= 4 * PROB_ELEMS) ? 1 : 0;

    dim3 grid(BLOCKS_X, NC);
    instanseg_kernel<<<grid, THREADS>>>(x, sigma, cvec, W1, b1, W2, b2, W3, b3,
                                        cent, out, write_iidd);
}